// round 16
// baseline (speedup 1.0000x reference)
#include <cuda_runtime.h>
#include <math_constants.h>
#include <cuda_bf16.h>
#include <cstdint>

#define NN 50000
#define NE 800000
#define HID 128

// ---------------- scratch ----------------
__device__ float g_img_f[NN * HID];
__device__ float g_txt_f[NN * HID];
__device__ float g_z[NN * HID];
__device__ float g_esrc[NN];
__device__ float g_edst[NN];
__device__ int   g_cnt[NN];
__device__ int   g_fill[NN];
__device__ int   g_row[NN + 1];
__device__ int   g_eidx[NE];
__device__ int   g_bsum[64];

// pre-converted GEMM weights: [pair][128] hi/lo bf16x2 (img first, then txt)
#define WB_PAIRS ((2048 / 2) + (768 / 2))
__device__ unsigned g_wbhi[WB_PAIRS * 128];
__device__ unsigned g_wblo[WB_PAIRS * 128];

// pre-converted node weights: pairs layout [pair][128]
#define OFF_IW1 0
#define OFF_IW2 128
#define OFF_TW1 192
#define OFF_TW2 320
#define OFF_CW  384
#define OFF_FW  512
#define NW_PAIRS 576
__device__ unsigned g_nwh[NW_PAIRS * 128];
__device__ unsigned g_nwl[NW_PAIRS * 128];

// ---------------- helpers ----------------
__device__ __forceinline__ unsigned pkbf2(float lo, float hi) {
    unsigned r; asm("cvt.rn.bf16x2.f32 %0, %1, %2;" : "=r"(r) : "f"(hi), "f"(lo));
    return r;
}
__device__ __forceinline__ float phi_(unsigned u) { return __uint_as_float(u & 0xffff0000u); }
__device__ __forceinline__ float plo_(unsigned u) { return __uint_as_float(u << 16); }
__device__ __forceinline__ uint2 split2(float x0, float x1) {
    unsigned h = pkbf2(x0, x1);
    return make_uint2(h, pkbf2(x0 - plo_(h), x1 - phi_(h)));
}
__device__ __forceinline__ void mma_bf16(float c[4], unsigned a0, unsigned a1,
                                         unsigned a2, unsigned a3,
                                         unsigned b0, unsigned b1) {
    asm volatile(
        "mma.sync.aligned.m16n8k16.row.col.f32.bf16.bf16.f32 "
        "{%0,%1,%2,%3}, {%4,%5,%6,%7}, {%8,%9}, {%0,%1,%2,%3};"
        : "+f"(c[0]), "+f"(c[1]), "+f"(c[2]), "+f"(c[3])
        : "r"(a0), "r"(a1), "r"(a2), "r"(a3), "r"(b0), "r"(b1));
}

// ---------------- CSR build ----------------
__global__ void k_zero(int n) {
    int i = blockIdx.x * blockDim.x + threadIdx.x;
    if (i < n) { g_cnt[i] = 0; g_fill[i] = 0; }
}

__global__ void k_count(const int* __restrict__ dst, int E) {
    int i = blockIdx.x * blockDim.x + threadIdx.x;
    if (i < E) atomicAdd(&g_cnt[dst[i]], 1);
}

__global__ __launch_bounds__(1024)
void k_scan1(int n) {
    __shared__ int sh[1024];
    int tid = threadIdx.x;
    int i = blockIdx.x * 1024 + tid;
    int v = (i < n) ? g_cnt[i] : 0;
    sh[tid] = v;
    __syncthreads();
    #pragma unroll
    for (int off = 1; off < 1024; off <<= 1) {
        int t = (tid >= off) ? sh[tid - off] : 0;
        __syncthreads();
        sh[tid] += t;
        __syncthreads();
    }
    if (i < n) g_row[i] = sh[tid] - v;
    if (tid == 1023) g_bsum[blockIdx.x] = sh[1023];
}

__global__ void k_scan2(int nblocks) {
    __shared__ int sh[64];
    int tid = threadIdx.x;
    int v = (tid < nblocks) ? g_bsum[tid] : 0;
    sh[tid] = v;
    __syncthreads();
    #pragma unroll
    for (int off = 1; off < 64; off <<= 1) {
        int t = (tid >= off) ? sh[tid - off] : 0;
        __syncthreads();
        sh[tid] += t;
        __syncthreads();
    }
    g_bsum[tid] = sh[tid] - v;
}

__global__ void k_scan3(int n, int E) {
    int i = blockIdx.x * blockDim.x + threadIdx.x;
    if (i < n) g_row[i] += g_bsum[i >> 10];
    if (i == 0) g_row[n] = E;
}

__global__ void k_scatter(const int* __restrict__ src, const int* __restrict__ dst, int E) {
    int i = blockIdx.x * blockDim.x + threadIdx.x;
    if (i >= E) return;
    int d = dst[i];
    int pos = g_row[d] + atomicAdd(&g_fill[d], 1);
    g_eidx[pos] = src[i];
}

// ---------------- weight pre-conversion ----------------
__global__ void k_prep(const float* __restrict__ Wi, const float* __restrict__ Wt,
                       int pairs_i, int pairs_t) {
    int i = blockIdx.x * blockDim.x + threadIdx.x;
    int total_i = pairs_i * 128;
    int total = total_i + pairs_t * 128;
    if (i >= total) return;
    const float* W;
    int p, n;
    if (i < total_i) { W = Wi; p = i >> 7; n = i & 127; }
    else             { W = Wt; int j = i - total_i; p = j >> 7; n = j & 127; }
    float f0 = W[(size_t)(2 * p) * 128 + n];
    float f1 = W[(size_t)(2 * p + 1) * 128 + n];
    unsigned h = pkbf2(f0, f1);
    g_wbhi[i] = h;
    g_wblo[i] = pkbf2(f0 - plo_(h), f1 - phi_(h));
}

__global__ void k_prep_node(const float* __restrict__ iW1, const float* __restrict__ iW2,
                            const float* __restrict__ tW1, const float* __restrict__ tW2,
                            const float* __restrict__ cW,  const float* __restrict__ fW) {
    int i = blockIdx.x * blockDim.x + threadIdx.x;
    if (i >= NW_PAIRS * 128) return;
    int pg = i >> 7, col = i & 127;
    const float* W; int p;
    if      (pg < OFF_IW2) { W = iW1; p = pg - OFF_IW1; }
    else if (pg < OFF_TW1) { W = iW2; p = pg - OFF_IW2; }
    else if (pg < OFF_TW2) { W = tW1; p = pg - OFF_TW1; }
    else if (pg < OFF_CW)  { W = tW2; p = pg - OFF_TW2; }
    else if (pg < OFF_FW)  { W = cW;  p = pg - OFF_CW; }
    else                   { W = fW;  p = pg - OFF_FW; }
    float w0 = W[(size_t)(2 * p) * 128 + col];
    float w1 = W[(size_t)(2 * p + 1) * 128 + col];
    unsigned h = pkbf2(w0, w1);
    g_nwh[i] = h;
    g_nwl[i] = pkbf2(w0 - plo_(h), w1 - phi_(h));
}

// ================= big input GEMMs: split-bf16, interleaved (hi,lo) smem =================
#define APLD 20    // uint2 per row; u32 stride 40: frag bank = 8*grp + 2*q, conflict-free
#define BPLD 140   // uint2 per row; u32 stride 280: frag bank = 24*q + 2*grp, conflict-free

struct MmaSmem {
    uint2 Ax[2][128][APLD];
    uint2 Bx[2][16][BPLD];
};
#define MMA_SMEM_BYTES ((int)sizeof(MmaSmem))

__global__ __launch_bounds__(256, 1)
void k_mma_gemm(const float* __restrict__ Ai, const float* __restrict__ At,
                float* __restrict__ Ci, float* __restrict__ Ct,
                int M, int Ki, int Kt) {
    extern __shared__ char smem_raw[];
    MmaSmem& s = *reinterpret_cast<MmaSmem*>(smem_raw);
    int sel = blockIdx.y;
    const float* A = sel ? At : Ai;
    float*       C = sel ? Ct : Ci;
    int K = sel ? Kt : Ki;
    const unsigned* wbh = g_wbhi + (sel ? (Ki >> 1) * 128 : 0);
    const unsigned* wbl = g_wblo + (sel ? (Ki >> 1) * 128 : 0);
    int ntile = K >> 5;

    int tid  = threadIdx.x;
    int warp = tid >> 5, lane = tid & 31;
    int wm = warp & 1;
    int wn = warp >> 1;
    int grp = lane >> 2, q = lane & 3;
    int m0 = blockIdx.x * 128;

    int ar[4], ac4[4];
    #pragma unroll
    for (int i = 0; i < 4; ++i) { int f4 = tid + i * 256; ar[i] = f4 >> 3; ac4[i] = f4 & 7; }
    int bkp[8], bc[8];
    #pragma unroll
    for (int i = 0; i < 8; ++i) { int idx = tid + i * 256; bkp[i] = idx >> 7; bc[i] = idx & 127; }

    float4 apf[4];
    unsigned bph[8], bpl[8];

    auto load_tile = [&](int k0) {
        #pragma unroll
        for (int i = 0; i < 4; ++i) {
            apf[i] = make_float4(0.f, 0.f, 0.f, 0.f);
            if (m0 + ar[i] < M)
                apf[i] = *(const float4*)&A[(size_t)(m0 + ar[i]) * K + k0 + ac4[i] * 4];
        }
        int pb = (k0 >> 1);
        #pragma unroll
        for (int i = 0; i < 8; ++i) {
            int idx = (pb + bkp[i]) * 128 + bc[i];
            bph[i] = wbh[idx];
            bpl[i] = wbl[idx];
        }
    };

    auto store_tile = [&](int buf) {
        #pragma unroll
        for (int i = 0; i < 4; ++i) {
            unsigned h0 = pkbf2(apf[i].x, apf[i].y);
            unsigned h1 = pkbf2(apf[i].z, apf[i].w);
            unsigned l0 = pkbf2(apf[i].x - plo_(h0), apf[i].y - phi_(h0));
            unsigned l1 = pkbf2(apf[i].z - plo_(h1), apf[i].w - phi_(h1));
            *(uint4*)&s.Ax[buf][ar[i]][2 * ac4[i]] = make_uint4(h0, l0, h1, l1);
        }
        #pragma unroll
        for (int i = 0; i < 8; ++i)
            s.Bx[buf][bkp[i]][bc[i]] = make_uint2(bph[i], bpl[i]);
    };

    float acc[4][4][4];
    #pragma unroll
    for (int i = 0; i < 4; ++i)
        #pragma unroll
        for (int j = 0; j < 4; ++j)
            #pragma unroll
            for (int k = 0; k < 4; ++k) acc[i][j][k] = 0.f;

    load_tile(0);
    store_tile(0);
    __syncthreads();

    #pragma unroll 1
    for (int t = 0; t < ntile; ++t) {
        int buf = t & 1;
        if (t + 1 < ntile) load_tile((t + 1) * 32);

        #pragma unroll
        for (int sstep = 0; sstep < 2; ++sstep) {
            int p = sstep * 8 + q;
            unsigned ah[4][4], al[4][4], bh[4][2], bl[4][2];
            #pragma unroll
            for (int mt = 0; mt < 4; ++mt) {
                int m = wm * 64 + mt * 16 + grp;
                uint2 v0 = s.Ax[buf][m][p];
                uint2 v1 = s.Ax[buf][m + 8][p];
                uint2 v2 = s.Ax[buf][m][p + 4];
                uint2 v3 = s.Ax[buf][m + 8][p + 4];
                ah[mt][0] = v0.x; al[mt][0] = v0.y;
                ah[mt][1] = v1.x; al[mt][1] = v1.y;
                ah[mt][2] = v2.x; al[mt][2] = v2.y;
                ah[mt][3] = v3.x; al[mt][3] = v3.y;
            }
            #pragma unroll
            for (int nt = 0; nt < 4; ++nt) {
                int n = wn * 32 + nt * 8 + grp;
                uint2 u0 = s.Bx[buf][p][n];
                uint2 u1 = s.Bx[buf][p + 4][n];
                bh[nt][0] = u0.x; bl[nt][0] = u0.y;
                bh[nt][1] = u1.x; bl[nt][1] = u1.y;
            }
            #pragma unroll
            for (int mt = 0; mt < 4; ++mt)
                #pragma unroll
                for (int nt = 0; nt < 4; ++nt) {
                    mma_bf16(acc[mt][nt], ah[mt][0], ah[mt][1], ah[mt][2], ah[mt][3],
                             bh[nt][0], bh[nt][1]);
                    mma_bf16(acc[mt][nt], ah[mt][0], ah[mt][1], ah[mt][2], ah[mt][3],
                             bl[nt][0], bl[nt][1]);
                    mma_bf16(acc[mt][nt], al[mt][0], al[mt][1], al[mt][2], al[mt][3],
                             bh[nt][0], bh[nt][1]);
                }
        }

        if (t + 1 < ntile) store_tile((t + 1) & 1);
        __syncthreads();
    }

    #pragma unroll
    for (int mt = 0; mt < 4; ++mt) {
        int m = m0 + wm * 64 + mt * 16 + grp;
        #pragma unroll
        for (int nt = 0; nt < 4; ++nt) {
            int n = wn * 32 + nt * 8 + 2 * q;
            if (m < M)
                *(float2*)&C[(size_t)m * 128 + n] = make_float2(acc[mt][nt][0], acc[mt][nt][1]);
            if (m + 8 < M)
                *(float2*)&C[(size_t)(m + 8) * 128 + n] = make_float2(acc[mt][nt][2], acc[mt][nt][3]);
        }
    }
}

// ================= fused per-node pipeline v6: interleaved (hi,lo) uint2 smem =================
#define XP 68

struct SmemN {
    uint2 E[32][XP];
    uint2 A[32][XP];
    uint2 B[32][XP];
    uint2 H[32][XP];
    float red[32][8][2];
    float g[32];
};
#define NODE_SMEM_BYTES ((int)sizeof(SmemN))

__device__ __forceinline__ void zacc(float acc[2][2][4]) {
    #pragma unroll
    for (int i = 0; i < 2; ++i)
        #pragma unroll
        for (int j = 0; j < 2; ++j)
            #pragma unroll
            for (int k = 0; k < 4; ++k) acc[i][j][k] = 0.f;
}

// gate passes: hh + lh (A error compensated; W hi only)
__device__ __forceinline__ void npassG(const uint2 (*__restrict__ X)[XP],
                                       int woff,
                                       float acc[2][2][4], int n0, int grp, int q) {
    #pragma unroll
    for (int c = 0; c < 8; ++c) {
        int pb = c * 8;
        unsigned ah[2][4], al[2][4], b[2][2];
        #pragma unroll
        for (int mt = 0; mt < 2; ++mt) {
            int r = mt * 16 + grp;
            uint2 v0 = X[r][pb + q];
            uint2 v1 = X[r + 8][pb + q];
            uint2 v2 = X[r][pb + q + 4];
            uint2 v3 = X[r + 8][pb + q + 4];
            ah[mt][0] = v0.x; al[mt][0] = v0.y;
            ah[mt][1] = v1.x; al[mt][1] = v1.y;
            ah[mt][2] = v2.x; al[mt][2] = v2.y;
            ah[mt][3] = v3.x; al[mt][3] = v3.y;
        }
        int pbase = woff + c * 8;
        #pragma unroll
        for (int nt = 0; nt < 2; ++nt) {
            int col = n0 + nt * 8 + grp;
            b[nt][0] = __ldg(&g_nwh[(pbase + q) * 128 + col]);
            b[nt][1] = __ldg(&g_nwh[(pbase + q + 4) * 128 + col]);
        }
        #pragma unroll
        for (int mt = 0; mt < 2; ++mt)
            #pragma unroll
            for (int nt = 0; nt < 2; ++nt) {
                mma_bf16(acc[mt][nt], ah[mt][0], ah[mt][1], ah[mt][2], ah[mt][3],
                         b[nt][0], b[nt][1]);
                mma_bf16(acc[mt][nt], al[mt][0], al[mt][1], al[mt][2], al[mt][3],
                         b[nt][0], b[nt][1]);
            }
    }
}

// value passes: hh + hl + lh (~2^-16)
__device__ __forceinline__ void npassV(const uint2 (*__restrict__ X)[XP],
                                       int woff,
                                       float acc[2][2][4], int n0, int grp, int q) {
    #pragma unroll
    for (int c = 0; c < 8; ++c) {
        int pb = c * 8;
        unsigned ah[2][4], al[2][4], bh[2][2], bl[2][2];
        #pragma unroll
        for (int mt = 0; mt < 2; ++mt) {
            int r = mt * 16 + grp;
            uint2 v0 = X[r][pb + q];
            uint2 v1 = X[r + 8][pb + q];
            uint2 v2 = X[r][pb + q + 4];
            uint2 v3 = X[r + 8][pb + q + 4];
            ah[mt][0] = v0.x; al[mt][0] = v0.y;
            ah[mt][1] = v1.x; al[mt][1] = v1.y;
            ah[mt][2] = v2.x; al[mt][2] = v2.y;
            ah[mt][3] = v3.x; al[mt][3] = v3.y;
        }
        int pbase = woff + c * 8;
        #pragma unroll
        for (int nt = 0; nt < 2; ++nt) {
            int col = n0 + nt * 8 + grp;
            bh[nt][0] = __ldg(&g_nwh[(pbase + q) * 128 + col]);
            bh[nt][1] = __ldg(&g_nwh[(pbase + q + 4) * 128 + col]);
            bl[nt][0] = __ldg(&g_nwl[(pbase + q) * 128 + col]);
            bl[nt][1] = __ldg(&g_nwl[(pbase + q + 4) * 128 + col]);
        }
        #pragma unroll
        for (int mt = 0; mt < 2; ++mt)
            #pragma unroll
            for (int nt = 0; nt < 2; ++nt) {
                mma_bf16(acc[mt][nt], ah[mt][0], ah[mt][1], ah[mt][2], ah[mt][3],
                         bh[nt][0], bh[nt][1]);
                mma_bf16(acc[mt][nt], ah[mt][0], ah[mt][1], ah[mt][2], ah[mt][3],
                         bl[nt][0], bl[nt][1]);
                mma_bf16(acc[mt][nt], al[mt][0], al[mt][1], al[mt][2], al[mt][3],
                         bh[nt][0], bh[nt][1]);
            }
    }
}

// relu(acc + bias) -> H pairs
__device__ __forceinline__ void relu_store(SmemN& s, float acc[2][2][4],
                                           const float* __restrict__ bp,
                                           int n0, int grp, int q) {
    #pragma unroll
    for (int nt = 0; nt < 2; ++nt) {
        int colp = (n0 >> 1) + nt * 4 + q;
        float2 b = __ldg((const float2*)&bp[2 * colp]);
        #pragma unroll
        for (int mt = 0; mt < 2; ++mt) {
            int r1 = mt * 16 + grp;
            s.H[r1][colp] = split2(fmaxf(acc[mt][nt][0] + b.x, 0.f),
                                   fmaxf(acc[mt][nt][1] + b.y, 0.f));
            s.H[r1 + 8][colp] = split2(fmaxf(acc[mt][nt][2] + b.x, 0.f),
                                       fmaxf(acc[mt][nt][3] + b.y, 0.f));
        }
    }
}

__device__ __forceinline__ void gate_finish(SmemN& s, float acc[2][2][4],
                                            const float* __restrict__ b2p,
                                            const float* __restrict__ w3p,
                                            const float* __restrict__ b3p,
                                            int n0, int grp, int q, int warp, int tid) {
    float part[4] = {0.f, 0.f, 0.f, 0.f};
    #pragma unroll
    for (int nt = 0; nt < 2; ++nt) {
        int col = n0 + nt * 8 + 2 * q;
        float2 b2 = __ldg((const float2*)&b2p[col]);
        float2 w3 = __ldg((const float2*)&w3p[col]);
        #pragma unroll
        for (int mt = 0; mt < 2; ++mt) {
            part[mt * 2 + 0] += fmaxf(acc[mt][nt][0] + b2.x, 0.f) * w3.x
                              + fmaxf(acc[mt][nt][1] + b2.y, 0.f) * w3.y;
            part[mt * 2 + 1] += fmaxf(acc[mt][nt][2] + b2.x, 0.f) * w3.x
                              + fmaxf(acc[mt][nt][3] + b2.y, 0.f) * w3.y;
        }
    }
    #pragma unroll
    for (int i = 0; i < 4; ++i) {
        part[i] += __shfl_xor_sync(0xffffffffu, part[i], 1);
        part[i] += __shfl_xor_sync(0xffffffffu, part[i], 2);
    }
    if (q == 0) {
        #pragma unroll
        for (int mt = 0; mt < 2; ++mt) {
            s.red[mt * 16 + grp][warp][0]     = part[mt * 2 + 0];
            s.red[mt * 16 + grp + 8][warp][0] = part[mt * 2 + 1];
        }
    }
    __syncthreads();
    if (tid < 32) {
        float v = 0.f;
        #pragma unroll
        for (int w = 0; w < 8; ++w) v += s.red[tid][w][0];
        s.g[tid] = 1.f / (1.f + expf(-(v + __ldg(b3p))));
    }
    __syncthreads();
}

// gated mix of pair arrays: X = g*X + (1-g)*E
__device__ __forceinline__ void mix_pairs(uint2 (*__restrict__ X)[XP],
                                          const uint2 (*__restrict__ El)[XP],
                                          const float* __restrict__ gv_, int r8, int c32) {
    #pragma unroll
    for (int i = 0; i < 4; ++i) {
        int r = r8 * 4 + i;
        float gv = gv_[r];
        #pragma unroll
        for (int pp = 0; pp < 2; ++pp) {
            int p = 2 * c32 + pp;
            uint2 xv = X[r][p];
            uint2 ev = El[r][p];
            float x0 = plo_(xv.x) + plo_(xv.y), x1 = phi_(xv.x) + phi_(xv.y);
            float e0 = plo_(ev.x) + plo_(ev.y), e1 = phi_(ev.x) + phi_(ev.y);
            X[r][p] = split2(gv * x0 + (1.f - gv) * e0, gv * x1 + (1.f - gv) * e1);
        }
    }
}

__global__ __launch_bounds__(256, 3)
void k_node(const int* __restrict__ node_id, const float* __restrict__ emb,
            const float* __restrict__ ib1, const float* __restrict__ ib2,
            const float* __restrict__ iW3, const float* __restrict__ ib3,
            const float* __restrict__ tb1, const float* __restrict__ tb2,
            const float* __restrict__ tW3, const float* __restrict__ tb3,
            const float* __restrict__ cb,  const float* __restrict__ attn_a,
            int N) {
    extern __shared__ char smem_raw[];
    SmemN& s = *reinterpret_cast<SmemN*>(smem_raw);
    int tid = threadIdx.x;
    int warp = tid >> 5, lane = tid & 31;
    int grp = lane >> 2, q = lane & 3;
    int n0 = warp * 16;
    int r8 = tid >> 5, c32 = tid & 31;
    int base = blockIdx.x * 32;

    #pragma unroll
    for (int it = 0; it < 4; ++it) {
        int idx = tid + it * 256;
        int n = idx >> 5, c4 = idx & 31;
        int gn = base + n;
        int nid = (gn < N) ? __ldg(&node_id[gn]) : 0;
        float4 ev = *(const float4*)&emb[(size_t)nid * 128 + c4 * 4];
        s.E[n][2 * c4]     = split2(ev.x, ev.y);
        s.E[n][2 * c4 + 1] = split2(ev.z, ev.w);
        float4 iv = make_float4(0.f, 0.f, 0.f, 0.f);
        float4 tv = make_float4(0.f, 0.f, 0.f, 0.f);
        if (gn < N) {
            iv = *(const float4*)&g_img_f[(size_t)gn * 128 + c4 * 4];
            tv = *(const float4*)&g_txt_f[(size_t)gn * 128 + c4 * 4];
        }
        s.A[n][2 * c4]     = split2(iv.x, iv.y);
        s.A[n][2 * c4 + 1] = split2(iv.z, iv.w);
        s.B[n][2 * c4]     = split2(tv.x, tv.y);
        s.B[n][2 * c4 + 1] = split2(tv.z, tv.w);
    }
    __syncthreads();

    float acc[2][2][4];

    // ==== img gate MLP ====
    zacc(acc);
    npassG(s.E, OFF_IW1,      acc, n0, grp, q);
    npassG(s.A, OFF_IW1 + 64, acc, n0, grp, q);
    relu_store(s, acc, ib1, n0, grp, q);
    __syncthreads();

    zacc(acc);
    npassG(s.H, OFF_IW2, acc, n0, grp, q);
    gate_finish(s, acc, ib2, iW3, ib3, n0, grp, q, warp, tid);

    mix_pairs(s.A, s.E, s.g, r8, c32);

    // ==== txt gate MLP ====
    zacc(acc);
    npassG(s.E, OFF_TW1,      acc, n0, grp, q);
    npassG(s.B, OFF_TW1 + 64, acc, n0, grp, q);
    relu_store(s, acc, tb1, n0, grp, q);
    __syncthreads();

    zacc(acc);
    npassG(s.H, OFF_TW2, acc, n0, grp, q);
    gate_finish(s, acc, tb2, tW3, tb3, n0, grp, q, warp, tid);

    mix_pairs(s.B, s.E, s.g, r8, c32);
    __syncthreads();

    // ==== comb gate (linear) + h ====
    zacc(acc);
    npassV(s.A, OFF_CW,      acc, n0, grp, q);
    npassV(s.B, OFF_CW + 64, acc, n0, grp, q);
    {
        #pragma unroll
        for (int nt = 0; nt < 2; ++nt) {
            int colp = (n0 >> 1) + nt * 4 + q;
            float2 cbv = __ldg((const float2*)&cb[2 * colp]);
            #pragma unroll
            for (int mt = 0; mt < 2; ++mt) {
                int r1 = mt * 16 + grp, r2 = r1 + 8;
                float g0 = acc[mt][nt][0] + cbv.x;
                float g1 = acc[mt][nt][1] + cbv.y;
                float g2 = acc[mt][nt][2] + cbv.x;
                float g3 = acc[mt][nt][3] + cbv.y;
                uint2 a1 = s.A[r1][colp], b1 = s.B[r1][colp];
                uint2 a2 = s.A[r2][colp], b2 = s.B[r2][colp];
                float av0 = plo_(a1.x) + plo_(a1.y), av1 = phi_(a1.x) + phi_(a1.y);
                float bv0 = plo_(b1.x) + plo_(b1.y), bv1 = phi_(b1.x) + phi_(b1.y);
                float aw0 = plo_(a2.x) + plo_(a2.y), aw1 = phi_(a2.x) + phi_(a2.y);
                float bw0 = plo_(b2.x) + plo_(b2.y), bw1 = phi_(b2.x) + phi_(b2.y);
                s.H[r1][colp] = split2(g0 * av0 + (1.f - g0) * bv0,
                                       g1 * av1 + (1.f - g1) * bv1);
                s.H[r2][colp] = split2(g2 * aw0 + (1.f - g2) * bw0,
                                       g3 * aw1 + (1.f - g3) * bw1);
            }
        }
    }
    __syncthreads();

    // ==== z = h @ fc_W ; z store + attention logits ====
    zacc(acc);
    npassV(s.H, OFF_FW, acc, n0, grp, q);
    {
        float p1[4] = {0.f, 0.f, 0.f, 0.f};
        float p2[4] = {0.f, 0.f, 0.f, 0.f};
        #pragma unroll
        for (int nt = 0; nt < 2; ++nt) {
            int col = n0 + nt * 8 + 2 * q;
            float2 a1 = __ldg((const float2*)&attn_a[col]);
            float2 a2 = __ldg((const float2*)&attn_a[128 + col]);
            #pragma unroll
            for (int mt = 0; mt < 2; ++mt) {
                int r1 = mt * 16 + grp, r2 = r1 + 8;
                int g1_ = base + r1, g2_ = base + r2;
                if (g1_ < N)
                    *(float2*)&g_z[(size_t)g1_ * 128 + col] =
                        make_float2(acc[mt][nt][0], acc[mt][nt][1]);
                if (g2_ < N)
                    *(float2*)&g_z[(size_t)g2_ * 128 + col] =
                        make_float2(acc[mt][nt][2], acc[mt][nt][3]);
                p1[mt * 2 + 0] += acc[mt][nt][0] * a1.x + acc[mt][nt][1] * a1.y;
                p1[mt * 2 + 1] += acc[mt][nt][2] * a1.x + acc[mt][nt][3] * a1.y;
                p2[mt * 2 + 0] += acc[mt][nt][0] * a2.x + acc[mt][nt][1] * a2.y;
                p2[mt * 2 + 1] += acc[mt][nt][2] * a2.x + acc[mt][nt][3] * a2.y;
            }
        }
        #pragma unroll
        for (int i = 0; i < 4; ++i) {
            p1[i] += __shfl_xor_sync(0xffffffffu, p1[i], 1);
            p1[i] += __shfl_xor_sync(0xffffffffu, p1[i], 2);
            p2[i] += __shfl_xor_sync(0xffffffffu, p2[i], 1);
            p2[i] += __shfl_xor_sync(0xffffffffu, p2[i], 2);
        }
        if (q == 0) {
            #pragma unroll
            for (int mt = 0; mt < 2; ++mt) {
                s.red[mt * 16 + grp][warp][0]     = p1[mt * 2 + 0];
                s.red[mt * 16 + grp + 8][warp][0] = p1[mt * 2 + 1];
                s.red[mt * 16 + grp][warp][1]     = p2[mt * 2 + 0];
                s.red[mt * 16 + grp + 8][warp][1] = p2[mt * 2 + 1];
            }
        }
        __syncthreads();
        if (tid < 32) {
            float v1 = 0.f, v2 = 0.f;
            #pragma unroll
            for (int w = 0; w < 8; ++w) { v1 += s.red[tid][w][0]; v2 += s.red[tid][w][1]; }
            int gn = base + tid;
            if (gn < N) { g_esrc[gn] = v1; g_edst[gn] = v2; }
        }
    }
}

// ---------------- CSR aggregate: warp per dst node, no atomics ----------------
__global__ __launch_bounds__(256)
void k_agg(float* __restrict__ out, int N) {
    int w = (int)((blockIdx.x * (size_t)blockDim.x + threadIdx.x) >> 5);
    int lane = threadIdx.x & 31;
    if (w >= N) return;
    int beg = g_row[w], end = g_row[w + 1];
    float ed = g_edst[w];

    float m = -CUDART_INF_F;
    for (int i = beg + lane; i < end; i += 32) {
        float e = g_esrc[g_eidx[i]] + ed;
        e = (e >= 0.f) ? e : 0.01f * e;
        m = fmaxf(m, e);
    }
    #pragma unroll
    for (int off = 16; off > 0; off >>= 1)
        m = fmaxf(m, __shfl_xor_sync(0xffffffffu, m, off));

    float4 acc = make_float4(0.f, 0.f, 0.f, 0.f);
    float denom = 0.f;
    for (int basei = beg; basei < end; basei += 32) {
        int idx = basei + lane;
        float wgt = 0.f; int sj = 0;
        if (idx < end) {
            sj = g_eidx[idx];
            float e = g_esrc[sj] + ed;
            e = (e >= 0.f) ? e : 0.01f * e;
            wgt = expf(e - m);
        }
        int cnt = min(32, end - basei);
        for (int j = 0; j < cnt; ++j) {
            float wj = __shfl_sync(0xffffffffu, wgt, j);
            int   s_ = __shfl_sync(0xffffffffu, sj, j);
            float4 zv = __ldg((const float4*)&g_z[(size_t)s_ * 128 + lane * 4]);
            acc.x = fmaf(wj, zv.x, acc.x);
            acc.y = fmaf(wj, zv.y, acc.y);
            acc.z = fmaf(wj, zv.z, acc.z);
            acc.w = fmaf(wj, zv.w, acc.w);
            denom += wj;
        }
    }
    float inv = (denom > 1e-20f) ? 1.f / denom : 0.f;
    acc.x *= inv; acc.y *= inv; acc.z *= inv; acc.w *= inv;
    *(float4*)&out[(size_t)w * 128 + lane * 4] = acc;
}

// ---------------- launch ----------------
extern "C" void kernel_launch(void* const* d_in, const int* in_sizes, int n_in,
                              void* d_out, int out_size) {
    const int*   node_id = (const int*)  d_in[0];
    const float* img_h   = (const float*)d_in[1];
    const float* txt_h   = (const float*)d_in[2];
    const int*   src     = (const int*)  d_in[3];
    const int*   dst     = (const int*)  d_in[4];
    const float* emb     = (const float*)d_in[5];
    const float* W_img   = (const float*)d_in[6];
    const float* iW1     = (const float*)d_in[7];
    const float* ib1     = (const float*)d_in[8];
    const float* iW2     = (const float*)d_in[9];
    const float* ib2     = (const float*)d_in[10];
    const float* iW3     = (const float*)d_in[11];
    const float* ib3     = (const float*)d_in[12];
    const float* W_txt   = (const float*)d_in[13];
    const float* tW1     = (const float*)d_in[14];
    const float* tb1     = (const float*)d_in[15];
    const float* tW2     = (const float*)d_in[16];
    const float* tb2     = (const float*)d_in[17];
    const float* tW3     = (const float*)d_in[18];
    const float* tb3     = (const float*)d_in[19];
    const float* cW      = (const float*)d_in[20];
    const float* cb      = (const float*)d_in[21];
    const float* fW      = (const float*)d_in[22];
    const float* attn_a  = (const float*)d_in[23];

    int N = in_sizes[0];
    int E = in_sizes[3];
    int IMG_D = in_sizes[1] / N;
    int TXT_D = in_sizes[2] / N;
    float* out = (float*)d_out;

    float *p_img_f, *p_txt_f;
    cudaGetSymbolAddress((void**)&p_img_f, g_img_f);
    cudaGetSymbolAddress((void**)&p_txt_f, g_txt_f);

    cudaFuncSetAttribute(k_node, cudaFuncAttributeMaxDynamicSharedMemorySize, NODE_SMEM_BYTES);
    cudaFuncSetAttribute(k_mma_gemm, cudaFuncAttributeMaxDynamicSharedMemorySize, MMA_SMEM_BYTES);

    int pairs_i = IMG_D / 2, pairs_t = TXT_D / 2;
    int prep_tot = (pairs_i + pairs_t) * 128;
    int nblocks_scan = (N + 1023) / 1024;

    // slot 3 = k_mma_gemm (ncu captures launch index 3)
    k_prep<<<(prep_tot + 255) / 256, 256>>>(W_img, W_txt, pairs_i, pairs_t);   // 0
    k_prep_node<<<(NW_PAIRS * 128 + 255) / 256, 256>>>(iW1, iW2, tW1, tW2, cW, fW); // 1
    k_zero<<<(N + 255) / 256, 256>>>(N);                        // 2
    dim3 ggrid((N + 127) / 128, 2);
    k_mma_gemm<<<ggrid, 256, MMA_SMEM_BYTES>>>(img_h, txt_h,
                                               p_img_f, p_txt_f, N, IMG_D, TXT_D); // 3
    k_count<<<(E + 255) / 256, 256>>>(dst, E);                  // 4
    k_scan1<<<nblocks_scan, 1024>>>(N);                         // 5
    k_scan2<<<1, 64>>>(nblocks_scan);                           // 6
    k_scan3<<<(N + 255) / 256, 256>>>(N, E);                    // 7
    k_scatter<<<(E + 255) / 256, 256>>>(src, dst, E);           // 8
    k_node<<<(N + 31) / 32, 256, NODE_SMEM_BYTES>>>(            // 9
        node_id, emb,
        ib1, ib2, iW3, ib3,
        tb1, tb2, tW3, tb3,
        cb, attn_a, N);
    k_agg<<<(N * 32 + 255) / 256, 256>>>(out, N);               // 10
}

// round 17
// speedup vs baseline: 1.5202x; 1.5202x over previous
#include <cuda_runtime.h>
#include <math_constants.h>
#include <cuda_bf16.h>
#include <cuda_fp16.h>
#include <cstdint>

#define NN 50000
#define NE 800000
#define HID 128

// ---------------- scratch ----------------
__device__ float g_img_f[NN * HID];
__device__ float g_txt_f[NN * HID];
__device__ float g_z[NN * HID];
__device__ float g_esrc[NN];
__device__ float g_edst[NN];
__device__ int   g_cnt[NN];
__device__ int   g_fill[NN];
__device__ int   g_row[NN + 1];
__device__ int   g_eidx[NE];
__device__ int   g_bsum[64];

// pre-converted GEMM weights: [pair][128] fp16x2 (img first, then txt)
#define WB_PAIRS ((2048 / 2) + (768 / 2))
__device__ unsigned g_wfh[WB_PAIRS * 128];

// pre-converted node weights: pairs layout [pair][128] (bf16 hi/lo)
#define OFF_IW1 0
#define OFF_IW2 128
#define OFF_TW1 192
#define OFF_TW2 320
#define OFF_CW  384
#define OFF_FW  512
#define NW_PAIRS 576
__device__ unsigned g_nwh[NW_PAIRS * 128];
__device__ unsigned g_nwl[NW_PAIRS * 128];

// ---------------- helpers ----------------
__device__ __forceinline__ unsigned pkbf2(float lo, float hi) {
    unsigned r; asm("cvt.rn.bf16x2.f32 %0, %1, %2;" : "=r"(r) : "f"(hi), "f"(lo));
    return r;
}
__device__ __forceinline__ unsigned pkhf2(float lo, float hi) {
    unsigned r; asm("cvt.rn.f16x2.f32 %0, %1, %2;" : "=r"(r) : "f"(hi), "f"(lo));
    return r;
}
__device__ __forceinline__ float phi_(unsigned u) { return __uint_as_float(u & 0xffff0000u); }
__device__ __forceinline__ float plo_(unsigned u) { return __uint_as_float(u << 16); }
__device__ __forceinline__ uint2 split2(float x0, float x1) {
    unsigned h = pkbf2(x0, x1);
    return make_uint2(h, pkbf2(x0 - plo_(h), x1 - phi_(h)));
}
__device__ __forceinline__ void mma_bf16(float c[4], unsigned a0, unsigned a1,
                                         unsigned a2, unsigned a3,
                                         unsigned b0, unsigned b1) {
    asm volatile(
        "mma.sync.aligned.m16n8k16.row.col.f32.bf16.bf16.f32 "
        "{%0,%1,%2,%3}, {%4,%5,%6,%7}, {%8,%9}, {%0,%1,%2,%3};"
        : "+f"(c[0]), "+f"(c[1]), "+f"(c[2]), "+f"(c[3])
        : "r"(a0), "r"(a1), "r"(a2), "r"(a3), "r"(b0), "r"(b1));
}
__device__ __forceinline__ void mma_f16(float c[4], unsigned a0, unsigned a1,
                                        unsigned a2, unsigned a3,
                                        unsigned b0, unsigned b1) {
    asm volatile(
        "mma.sync.aligned.m16n8k16.row.col.f32.f16.f16.f32 "
        "{%0,%1,%2,%3}, {%4,%5,%6,%7}, {%8,%9}, {%0,%1,%2,%3};"
        : "+f"(c[0]), "+f"(c[1]), "+f"(c[2]), "+f"(c[3])
        : "r"(a0), "r"(a1), "r"(a2), "r"(a3), "r"(b0), "r"(b1));
}

// ---------------- CSR build ----------------
__global__ void k_zero(int n) {
    int i = blockIdx.x * blockDim.x + threadIdx.x;
    if (i < n) { g_cnt[i] = 0; g_fill[i] = 0; }
}

__global__ void k_count(const int* __restrict__ dst, int E) {
    int i = blockIdx.x * blockDim.x + threadIdx.x;
    if (i < E) atomicAdd(&g_cnt[dst[i]], 1);
}

__global__ __launch_bounds__(1024)
void k_scan1(int n) {
    __shared__ int sh[1024];
    int tid = threadIdx.x;
    int i = blockIdx.x * 1024 + tid;
    int v = (i < n) ? g_cnt[i] : 0;
    sh[tid] = v;
    __syncthreads();
    #pragma unroll
    for (int off = 1; off < 1024; off <<= 1) {
        int t = (tid >= off) ? sh[tid - off] : 0;
        __syncthreads();
        sh[tid] += t;
        __syncthreads();
    }
    if (i < n) g_row[i] = sh[tid] - v;
    if (tid == 1023) g_bsum[blockIdx.x] = sh[1023];
}

__global__ void k_scan2(int nblocks) {
    __shared__ int sh[64];
    int tid = threadIdx.x;
    int v = (tid < nblocks) ? g_bsum[tid] : 0;
    sh[tid] = v;
    __syncthreads();
    #pragma unroll
    for (int off = 1; off < 64; off <<= 1) {
        int t = (tid >= off) ? sh[tid - off] : 0;
        __syncthreads();
        sh[tid] += t;
        __syncthreads();
    }
    g_bsum[tid] = sh[tid] - v;
}

__global__ void k_scan3(int n, int E) {
    int i = blockIdx.x * blockDim.x + threadIdx.x;
    if (i < n) g_row[i] += g_bsum[i >> 10];
    if (i == 0) g_row[n] = E;
}

__global__ void k_scatter(const int* __restrict__ src, const int* __restrict__ dst, int E) {
    int i = blockIdx.x * blockDim.x + threadIdx.x;
    if (i >= E) return;
    int d = dst[i];
    int pos = g_row[d] + atomicAdd(&g_fill[d], 1);
    g_eidx[pos] = src[i];
}

// ---------------- weight pre-conversion ----------------
__global__ void k_prep(const float* __restrict__ Wi, const float* __restrict__ Wt,
                       int pairs_i, int pairs_t) {
    int i = blockIdx.x * blockDim.x + threadIdx.x;
    int total_i = pairs_i * 128;
    int total = total_i + pairs_t * 128;
    if (i >= total) return;
    const float* W;
    int p, n;
    if (i < total_i) { W = Wi; p = i >> 7; n = i & 127; }
    else             { W = Wt; int j = i - total_i; p = j >> 7; n = j & 127; }
    float f0 = W[(size_t)(2 * p) * 128 + n];
    float f1 = W[(size_t)(2 * p + 1) * 128 + n];
    g_wfh[i] = pkhf2(f0, f1);
}

__global__ void k_prep_node(const float* __restrict__ iW1, const float* __restrict__ iW2,
                            const float* __restrict__ tW1, const float* __restrict__ tW2,
                            const float* __restrict__ cW,  const float* __restrict__ fW) {
    int i = blockIdx.x * blockDim.x + threadIdx.x;
    if (i >= NW_PAIRS * 128) return;
    int pg = i >> 7, col = i & 127;
    const float* W; int p;
    if      (pg < OFF_IW2) { W = iW1; p = pg - OFF_IW1; }
    else if (pg < OFF_TW1) { W = iW2; p = pg - OFF_IW2; }
    else if (pg < OFF_TW2) { W = tW1; p = pg - OFF_TW1; }
    else if (pg < OFF_CW)  { W = tW2; p = pg - OFF_TW2; }
    else if (pg < OFF_FW)  { W = cW;  p = pg - OFF_CW; }
    else                   { W = fW;  p = pg - OFF_FW; }
    float w0 = W[(size_t)(2 * p) * 128 + col];
    float w1 = W[(size_t)(2 * p + 1) * 128 + col];
    unsigned h = pkbf2(w0, w1);
    g_nwh[i] = h;
    g_nwl[i] = pkbf2(w0 - plo_(h), w1 - phi_(h));
}

// ================= big input GEMMs: plain fp16, 128-row tiles, double-buffered =================
#define APLD 20
#define BPLD 136

struct MmaSmem {
    unsigned Ax[2][128][APLD];
    unsigned Bx[2][16][BPLD];
};
#define MMA_SMEM_BYTES ((int)sizeof(MmaSmem))

__global__ __launch_bounds__(256, 2)
void k_mma_gemm(const float* __restrict__ Ai, const float* __restrict__ At,
                float* __restrict__ Ci, float* __restrict__ Ct,
                int M, int Ki, int Kt) {
    extern __shared__ char smem_raw[];
    MmaSmem& s = *reinterpret_cast<MmaSmem*>(smem_raw);
    int sel = blockIdx.y;
    const float* A = sel ? At : Ai;
    float*       C = sel ? Ct : Ci;
    int K = sel ? Kt : Ki;
    const unsigned* wfh = g_wfh + (sel ? (Ki >> 1) * 128 : 0);
    int ntile = K >> 5;

    int tid  = threadIdx.x;
    int warp = tid >> 5, lane = tid & 31;
    int wm = warp & 1;
    int wn = warp >> 1;
    int grp = lane >> 2, q = lane & 3;
    int m0 = blockIdx.x * 128;

    int ar[4], ac4[4];
    #pragma unroll
    for (int i = 0; i < 4; ++i) { int f4 = tid + i * 256; ar[i] = f4 >> 3; ac4[i] = f4 & 7; }
    int bkp[8], bc[8];
    #pragma unroll
    for (int i = 0; i < 8; ++i) { int idx = tid + i * 256; bkp[i] = idx >> 7; bc[i] = idx & 127; }

    float4 apf[4];
    unsigned bpf[8];

    auto load_tile = [&](int k0) {
        #pragma unroll
        for (int i = 0; i < 4; ++i) {
            apf[i] = make_float4(0.f, 0.f, 0.f, 0.f);
            if (m0 + ar[i] < M)
                apf[i] = *(const float4*)&A[(size_t)(m0 + ar[i]) * K + k0 + ac4[i] * 4];
        }
        int pb = (k0 >> 1);
        #pragma unroll
        for (int i = 0; i < 8; ++i)
            bpf[i] = wfh[(pb + bkp[i]) * 128 + bc[i]];
    };

    auto store_tile = [&](int buf) {
        #pragma unroll
        for (int i = 0; i < 4; ++i) {
            unsigned h0 = pkhf2(apf[i].x, apf[i].y);
            unsigned h1 = pkhf2(apf[i].z, apf[i].w);
            *(uint2*)&s.Ax[buf][ar[i]][2 * ac4[i]] = make_uint2(h0, h1);
        }
        #pragma unroll
        for (int i = 0; i < 8; ++i)
            s.Bx[buf][bkp[i]][bc[i]] = bpf[i];
    };

    float acc[4][4][4];
    #pragma unroll
    for (int i = 0; i < 4; ++i)
        #pragma unroll
        for (int j = 0; j < 4; ++j)
            #pragma unroll
            for (int k = 0; k < 4; ++k) acc[i][j][k] = 0.f;

    load_tile(0);
    store_tile(0);
    __syncthreads();

    #pragma unroll 1
    for (int t = 0; t < ntile; ++t) {
        int buf = t & 1;
        if (t + 1 < ntile) load_tile((t + 1) * 32);

        #pragma unroll
        for (int sstep = 0; sstep < 2; ++sstep) {
            int p = sstep * 8 + q;
            unsigned af[4][4], bh[4][2];
            #pragma unroll
            for (int mt = 0; mt < 4; ++mt) {
                int m = wm * 64 + mt * 16 + grp;
                af[mt][0] = s.Ax[buf][m][p];
                af[mt][1] = s.Ax[buf][m + 8][p];
                af[mt][2] = s.Ax[buf][m][p + 4];
                af[mt][3] = s.Ax[buf][m + 8][p + 4];
            }
            #pragma unroll
            for (int nt = 0; nt < 4; ++nt) {
                int n = wn * 32 + nt * 8 + grp;
                bh[nt][0] = s.Bx[buf][p][n];
                bh[nt][1] = s.Bx[buf][p + 4][n];
            }
            #pragma unroll
            for (int mt = 0; mt < 4; ++mt)
                #pragma unroll
                for (int nt = 0; nt < 4; ++nt)
                    mma_f16(acc[mt][nt], af[mt][0], af[mt][1], af[mt][2], af[mt][3],
                            bh[nt][0], bh[nt][1]);
        }

        if (t + 1 < ntile) store_tile((t + 1) & 1);
        __syncthreads();
    }

    #pragma unroll
    for (int mt = 0; mt < 4; ++mt) {
        int m = m0 + wm * 64 + mt * 16 + grp;
        #pragma unroll
        for (int nt = 0; nt < 4; ++nt) {
            int n = wn * 32 + nt * 8 + 2 * q;
            if (m < M)
                *(float2*)&C[(size_t)m * 128 + n] = make_float2(acc[mt][nt][0], acc[mt][nt][1]);
            if (m + 8 < M)
                *(float2*)&C[(size_t)(m + 8) * 128 + n] = make_float2(acc[mt][nt][2], acc[mt][nt][3]);
        }
    }
}

// ================= fused per-node pipeline v6: interleaved (hi,lo) uint2 smem =================
#define XP 68

struct SmemN {
    uint2 E[32][XP];
    uint2 A[32][XP];
    uint2 B[32][XP];
    uint2 H[32][XP];
    float red[32][8][2];
    float g[32];
};
#define NODE_SMEM_BYTES ((int)sizeof(SmemN))

__device__ __forceinline__ void zacc(float acc[2][2][4]) {
    #pragma unroll
    for (int i = 0; i < 2; ++i)
        #pragma unroll
        for (int j = 0; j < 2; ++j)
            #pragma unroll
            for (int k = 0; k < 4; ++k) acc[i][j][k] = 0.f;
}

// gate passes: hh + lh (A error compensated; W hi only)
__device__ __forceinline__ void npassG(const uint2 (*__restrict__ X)[XP],
                                       int woff,
                                       float acc[2][2][4], int n0, int grp, int q) {
    #pragma unroll
    for (int c = 0; c < 8; ++c) {
        int pb = c * 8;
        unsigned ah[2][4], al[2][4], b[2][2];
        #pragma unroll
        for (int mt = 0; mt < 2; ++mt) {
            int r = mt * 16 + grp;
            uint2 v0 = X[r][pb + q];
            uint2 v1 = X[r + 8][pb + q];
            uint2 v2 = X[r][pb + q + 4];
            uint2 v3 = X[r + 8][pb + q + 4];
            ah[mt][0] = v0.x; al[mt][0] = v0.y;
            ah[mt][1] = v1.x; al[mt][1] = v1.y;
            ah[mt][2] = v2.x; al[mt][2] = v2.y;
            ah[mt][3] = v3.x; al[mt][3] = v3.y;
        }
        int pbase = woff + c * 8;
        #pragma unroll
        for (int nt = 0; nt < 2; ++nt) {
            int col = n0 + nt * 8 + grp;
            b[nt][0] = __ldg(&g_nwh[(pbase + q) * 128 + col]);
            b[nt][1] = __ldg(&g_nwh[(pbase + q + 4) * 128 + col]);
        }
        #pragma unroll
        for (int mt = 0; mt < 2; ++mt)
            #pragma unroll
            for (int nt = 0; nt < 2; ++nt) {
                mma_bf16(acc[mt][nt], ah[mt][0], ah[mt][1], ah[mt][2], ah[mt][3],
                         b[nt][0], b[nt][1]);
                mma_bf16(acc[mt][nt], al[mt][0], al[mt][1], al[mt][2], al[mt][3],
                         b[nt][0], b[nt][1]);
            }
    }
}

// value passes: hh + hl + lh (~2^-16)
__device__ __forceinline__ void npassV(const uint2 (*__restrict__ X)[XP],
                                       int woff,
                                       float acc[2][2][4], int n0, int grp, int q) {
    #pragma unroll
    for (int c = 0; c < 8; ++c) {
        int pb = c * 8;
        unsigned ah[2][4], al[2][4], bh[2][2], bl[2][2];
        #pragma unroll
        for (int mt = 0; mt < 2; ++mt) {
            int r = mt * 16 + grp;
            uint2 v0 = X[r][pb + q];
            uint2 v1 = X[r + 8][pb + q];
            uint2 v2 = X[r][pb + q + 4];
            uint2 v3 = X[r + 8][pb + q + 4];
            ah[mt][0] = v0.x; al[mt][0] = v0.y;
            ah[mt][1] = v1.x; al[mt][1] = v1.y;
            ah[mt][2] = v2.x; al[mt][2] = v2.y;
            ah[mt][3] = v3.x; al[mt][3] = v3.y;
        }
        int pbase = woff + c * 8;
        #pragma unroll
        for (int nt = 0; nt < 2; ++nt) {
            int col = n0 + nt * 8 + grp;
            bh[nt][0] = __ldg(&g_nwh[(pbase + q) * 128 + col]);
            bh[nt][1] = __ldg(&g_nwh[(pbase + q + 4) * 128 + col]);
            bl[nt][0] = __ldg(&g_nwl[(pbase + q) * 128 + col]);
            bl[nt][1] = __ldg(&g_nwl[(pbase + q + 4) * 128 + col]);
        }
        #pragma unroll
        for (int mt = 0; mt < 2; ++mt)
            #pragma unroll
            for (int nt = 0; nt < 2; ++nt) {
                mma_bf16(acc[mt][nt], ah[mt][0], ah[mt][1], ah[mt][2], ah[mt][3],
                         bh[nt][0], bh[nt][1]);
                mma_bf16(acc[mt][nt], ah[mt][0], ah[mt][1], ah[mt][2], ah[mt][3],
                         bl[nt][0], bl[nt][1]);
                mma_bf16(acc[mt][nt], al[mt][0], al[mt][1], al[mt][2], al[mt][3],
                         bh[nt][0], bh[nt][1]);
            }
    }
}

// relu(acc + bias) -> H pairs
__device__ __forceinline__ void relu_store(SmemN& s, float acc[2][2][4],
                                           const float* __restrict__ bp,
                                           int n0, int grp, int q) {
    #pragma unroll
    for (int nt = 0; nt < 2; ++nt) {
        int colp = (n0 >> 1) + nt * 4 + q;
        float2 b = __ldg((const float2*)&bp[2 * colp]);
        #pragma unroll
        for (int mt = 0; mt < 2; ++mt) {
            int r1 = mt * 16 + grp;
            s.H[r1][colp] = split2(fmaxf(acc[mt][nt][0] + b.x, 0.f),
                                   fmaxf(acc[mt][nt][1] + b.y, 0.f));
            s.H[r1 + 8][colp] = split2(fmaxf(acc[mt][nt][2] + b.x, 0.f),
                                       fmaxf(acc[mt][nt][3] + b.y, 0.f));
        }
    }
}

__device__ __forceinline__ void gate_finish(SmemN& s, float acc[2][2][4],
                                            const float* __restrict__ b2p,
                                            const float* __restrict__ w3p,
                                            const float* __restrict__ b3p,
                                            int n0, int grp, int q, int warp, int tid) {
    float part[4] = {0.f, 0.f, 0.f, 0.f};
    #pragma unroll
    for (int nt = 0; nt < 2; ++nt) {
        int col = n0 + nt * 8 + 2 * q;
        float2 b2 = __ldg((const float2*)&b2p[col]);
        float2 w3 = __ldg((const float2*)&w3p[col]);
        #pragma unroll
        for (int mt = 0; mt < 2; ++mt) {
            part[mt * 2 + 0] += fmaxf(acc[mt][nt][0] + b2.x, 0.f) * w3.x
                              + fmaxf(acc[mt][nt][1] + b2.y, 0.f) * w3.y;
            part[mt * 2 + 1] += fmaxf(acc[mt][nt][2] + b2.x, 0.f) * w3.x
                              + fmaxf(acc[mt][nt][3] + b2.y, 0.f) * w3.y;
        }
    }
    #pragma unroll
    for (int i = 0; i < 4; ++i) {
        part[i] += __shfl_xor_sync(0xffffffffu, part[i], 1);
        part[i] += __shfl_xor_sync(0xffffffffu, part[i], 2);
    }
    if (q == 0) {
        #pragma unroll
        for (int mt = 0; mt < 2; ++mt) {
            s.red[mt * 16 + grp][warp][0]     = part[mt * 2 + 0];
            s.red[mt * 16 + grp + 8][warp][0] = part[mt * 2 + 1];
        }
    }
    __syncthreads();
    if (tid < 32) {
        float v = 0.f;
        #pragma unroll
        for (int w = 0; w < 8; ++w) v += s.red[tid][w][0];
        s.g[tid] = 1.f / (1.f + expf(-(v + __ldg(b3p))));
    }
    __syncthreads();
}

// gated mix of pair arrays: X = g*X + (1-g)*E
__device__ __forceinline__ void mix_pairs(uint2 (*__restrict__ X)[XP],
                                          const uint2 (*__restrict__ El)[XP],
                                          const float* __restrict__ gv_, int r8, int c32) {
    #pragma unroll
    for (int i = 0; i < 4; ++i) {
        int r = r8 * 4 + i;
        float gv = gv_[r];
        #pragma unroll
        for (int pp = 0; pp < 2; ++pp) {
            int p = 2 * c32 + pp;
            uint2 xv = X[r][p];
            uint2 ev = El[r][p];
            float x0 = plo_(xv.x) + plo_(xv.y), x1 = phi_(xv.x) + phi_(xv.y);
            float e0 = plo_(ev.x) + plo_(ev.y), e1 = phi_(ev.x) + phi_(ev.y);
            X[r][p] = split2(gv * x0 + (1.f - gv) * e0, gv * x1 + (1.f - gv) * e1);
        }
    }
}

__global__ __launch_bounds__(256, 3)
void k_node(const int* __restrict__ node_id, const float* __restrict__ emb,
            const float* __restrict__ ib1, const float* __restrict__ ib2,
            const float* __restrict__ iW3, const float* __restrict__ ib3,
            const float* __restrict__ tb1, const float* __restrict__ tb2,
            const float* __restrict__ tW3, const float* __restrict__ tb3,
            const float* __restrict__ cb,  const float* __restrict__ attn_a,
            int N) {
    extern __shared__ char smem_raw[];
    SmemN& s = *reinterpret_cast<SmemN*>(smem_raw);
    int tid = threadIdx.x;
    int warp = tid >> 5, lane = tid & 31;
    int grp = lane >> 2, q = lane & 3;
    int n0 = warp * 16;
    int r8 = tid >> 5, c32 = tid & 31;
    int base = blockIdx.x * 32;

    #pragma unroll
    for (int it = 0; it < 4; ++it) {
        int idx = tid + it * 256;
        int n = idx >> 5, c4 = idx & 31;
        int gn = base + n;
        int nid = (gn < N) ? __ldg(&node_id[gn]) : 0;
        float4 ev = *(const float4*)&emb[(size_t)nid * 128 + c4 * 4];
        s.E[n][2 * c4]     = split2(ev.x, ev.y);
        s.E[n][2 * c4 + 1] = split2(ev.z, ev.w);
        float4 iv = make_float4(0.f, 0.f, 0.f, 0.f);
        float4 tv = make_float4(0.f, 0.f, 0.f, 0.f);
        if (gn < N) {
            iv = *(const float4*)&g_img_f[(size_t)gn * 128 + c4 * 4];
            tv = *(const float4*)&g_txt_f[(size_t)gn * 128 + c4 * 4];
        }
        s.A[n][2 * c4]     = split2(iv.x, iv.y);
        s.A[n][2 * c4 + 1] = split2(iv.z, iv.w);
        s.B[n][2 * c4]     = split2(tv.x, tv.y);
        s.B[n][2 * c4 + 1] = split2(tv.z, tv.w);
    }
    __syncthreads();

    float acc[2][2][4];

    // ==== img gate MLP ====
    zacc(acc);
    npassG(s.E, OFF_IW1,      acc, n0, grp, q);
    npassG(s.A, OFF_IW1 + 64, acc, n0, grp, q);
    relu_store(s, acc, ib1, n0, grp, q);
    __syncthreads();

    zacc(acc);
    npassG(s.H, OFF_IW2, acc, n0, grp, q);
    gate_finish(s, acc, ib2, iW3, ib3, n0, grp, q, warp, tid);

    mix_pairs(s.A, s.E, s.g, r8, c32);

    // ==== txt gate MLP ====
    zacc(acc);
    npassG(s.E, OFF_TW1,      acc, n0, grp, q);
    npassG(s.B, OFF_TW1 + 64, acc, n0, grp, q);
    relu_store(s, acc, tb1, n0, grp, q);
    __syncthreads();

    zacc(acc);
    npassG(s.H, OFF_TW2, acc, n0, grp, q);
    gate_finish(s, acc, tb2, tW3, tb3, n0, grp, q, warp, tid);

    mix_pairs(s.B, s.E, s.g, r8, c32);
    __syncthreads();

    // ==== comb gate (linear) + h ====
    zacc(acc);
    npassV(s.A, OFF_CW,      acc, n0, grp, q);
    npassV(s.B, OFF_CW + 64, acc, n0, grp, q);
    {
        #pragma unroll
        for (int nt = 0; nt < 2; ++nt) {
            int colp = (n0 >> 1) + nt * 4 + q;
            float2 cbv = __ldg((const float2*)&cb[2 * colp]);
            #pragma unroll
            for (int mt = 0; mt < 2; ++mt) {
                int r1 = mt * 16 + grp, r2 = r1 + 8;
                float g0 = acc[mt][nt][0] + cbv.x;
                float g1 = acc[mt][nt][1] + cbv.y;
                float g2 = acc[mt][nt][2] + cbv.x;
                float g3 = acc[mt][nt][3] + cbv.y;
                uint2 a1 = s.A[r1][colp], b1 = s.B[r1][colp];
                uint2 a2 = s.A[r2][colp], b2 = s.B[r2][colp];
                float av0 = plo_(a1.x) + plo_(a1.y), av1 = phi_(a1.x) + phi_(a1.y);
                float bv0 = plo_(b1.x) + plo_(b1.y), bv1 = phi_(b1.x) + phi_(b1.y);
                float aw0 = plo_(a2.x) + plo_(a2.y), aw1 = phi_(a2.x) + phi_(a2.y);
                float bw0 = plo_(b2.x) + plo_(b2.y), bw1 = phi_(b2.x) + phi_(b2.y);
                s.H[r1][colp] = split2(g0 * av0 + (1.f - g0) * bv0,
                                       g1 * av1 + (1.f - g1) * bv1);
                s.H[r2][colp] = split2(g2 * aw0 + (1.f - g2) * bw0,
                                       g3 * aw1 + (1.f - g3) * bw1);
            }
        }
    }
    __syncthreads();

    // ==== z = h @ fc_W ; z store + attention logits ====
    zacc(acc);
    npassV(s.H, OFF_FW, acc, n0, grp, q);
    {
        float p1[4] = {0.f, 0.f, 0.f, 0.f};
        float p2[4] = {0.f, 0.f, 0.f, 0.f};
        #pragma unroll
        for (int nt = 0; nt < 2; ++nt) {
            int col = n0 + nt * 8 + 2 * q;
            float2 a1 = __ldg((const float2*)&attn_a[col]);
            float2 a2 = __ldg((const float2*)&attn_a[128 + col]);
            #pragma unroll
            for (int mt = 0; mt < 2; ++mt) {
                int r1 = mt * 16 + grp, r2 = r1 + 8;
                int g1_ = base + r1, g2_ = base + r2;
                if (g1_ < N)
                    *(float2*)&g_z[(size_t)g1_ * 128 + col] =
                        make_float2(acc[mt][nt][0], acc[mt][nt][1]);
                if (g2_ < N)
                    *(float2*)&g_z[(size_t)g2_ * 128 + col] =
                        make_float2(acc[mt][nt][2], acc[mt][nt][3]);
                p1[mt * 2 + 0] += acc[mt][nt][0] * a1.x + acc[mt][nt][1] * a1.y;
                p1[mt * 2 + 1] += acc[mt][nt][2] * a1.x + acc[mt][nt][3] * a1.y;
                p2[mt * 2 + 0] += acc[mt][nt][0] * a2.x + acc[mt][nt][1] * a2.y;
                p2[mt * 2 + 1] += acc[mt][nt][2] * a2.x + acc[mt][nt][3] * a2.y;
            }
        }
        #pragma unroll
        for (int i = 0; i < 4; ++i) {
            p1[i] += __shfl_xor_sync(0xffffffffu, p1[i], 1);
            p1[i] += __shfl_xor_sync(0xffffffffu, p1[i], 2);
            p2[i] += __shfl_xor_sync(0xffffffffu, p2[i], 1);
            p2[i] += __shfl_xor_sync(0xffffffffu, p2[i], 2);
        }
        if (q == 0) {
            #pragma unroll
            for (int mt = 0; mt < 2; ++mt) {
                s.red[mt * 16 + grp][warp][0]     = p1[mt * 2 + 0];
                s.red[mt * 16 + grp + 8][warp][0] = p1[mt * 2 + 1];
                s.red[mt * 16 + grp][warp][1]     = p2[mt * 2 + 0];
                s.red[mt * 16 + grp + 8][warp][1] = p2[mt * 2 + 1];
            }
        }
        __syncthreads();
        if (tid < 32) {
            float v1 = 0.f, v2 = 0.f;
            #pragma unroll
            for (int w = 0; w < 8; ++w) { v1 += s.red[tid][w][0]; v2 += s.red[tid][w][1]; }
            int gn = base + tid;
            if (gn < N) { g_esrc[gn] = v1; g_edst[gn] = v2; }
        }
    }
}

// ---------------- CSR aggregate: warp per dst node, no atomics ----------------
__global__ __launch_bounds__(256)
void k_agg(float* __restrict__ out, int N) {
    int w = (int)((blockIdx.x * (size_t)blockDim.x + threadIdx.x) >> 5);
    int lane = threadIdx.x & 31;
    if (w >= N) return;
    int beg = g_row[w], end = g_row[w + 1];
    float ed = g_edst[w];

    float m = -CUDART_INF_F;
    for (int i = beg + lane; i < end; i += 32) {
        float e = g_esrc[g_eidx[i]] + ed;
        e = (e >= 0.f) ? e : 0.01f * e;
        m = fmaxf(m, e);
    }
    #pragma unroll
    for (int off = 16; off > 0; off >>= 1)
        m = fmaxf(m, __shfl_xor_sync(0xffffffffu, m, off));

    float4 acc = make_float4(0.f, 0.f, 0.f, 0.f);
    float denom = 0.f;
    for (int basei = beg; basei < end; basei += 32) {
        int idx = basei + lane;
        float wgt = 0.f; int sj = 0;
        if (idx < end) {
            sj = g_eidx[idx];
            float e = g_esrc[sj] + ed;
            e = (e >= 0.f) ? e : 0.01f * e;
            wgt = expf(e - m);
        }
        int cnt = min(32, end - basei);
        for (int j = 0; j < cnt; ++j) {
            float wj = __shfl_sync(0xffffffffu, wgt, j);
            int   s_ = __shfl_sync(0xffffffffu, sj, j);
            float4 zv = __ldg((const float4*)&g_z[(size_t)s_ * 128 + lane * 4]);
            acc.x = fmaf(wj, zv.x, acc.x);
            acc.y = fmaf(wj, zv.y, acc.y);
            acc.z = fmaf(wj, zv.z, acc.z);
            acc.w = fmaf(wj, zv.w, acc.w);
            denom += wj;
        }
    }
    float inv = (denom > 1e-20f) ? 1.f / denom : 0.f;
    acc.x *= inv; acc.y *= inv; acc.z *= inv; acc.w *= inv;
    *(float4*)&out[(size_t)w * 128 + lane * 4] = acc;
}

// ---------------- launch ----------------
extern "C" void kernel_launch(void* const* d_in, const int* in_sizes, int n_in,
                              void* d_out, int out_size) {
    const int*   node_id = (const int*)  d_in[0];
    const float* img_h   = (const float*)d_in[1];
    const float* txt_h   = (const float*)d_in[2];
    const int*   src     = (const int*)  d_in[3];
    const int*   dst     = (const int*)  d_in[4];
    const float* emb     = (const float*)d_in[5];
    const float* W_img   = (const float*)d_in[6];
    const float* iW1     = (const float*)d_in[7];
    const float* ib1     = (const float*)d_in[8];
    const float* iW2     = (const float*)d_in[9];
    const float* ib2     = (const float*)d_in[10];
    const float* iW3     = (const float*)d_in[11];
    const float* ib3     = (const float*)d_in[12];
    const float* W_txt   = (const float*)d_in[13];
    const float* tW1     = (const float*)d_in[14];
    const float* tb1     = (const float*)d_in[15];
    const float* tW2     = (const float*)d_in[16];
    const float* tb2     = (const float*)d_in[17];
    const float* tW3     = (const float*)d_in[18];
    const float* tb3     = (const float*)d_in[19];
    const float* cW      = (const float*)d_in[20];
    const float* cb      = (const float*)d_in[21];
    const float* fW      = (const float*)d_in[22];
    const float* attn_a  = (const float*)d_in[23];

    int N = in_sizes[0];
    int E = in_sizes[3];
    int IMG_D = in_sizes[1] / N;
    int TXT_D = in_sizes[2] / N;
    float* out = (float*)d_out;

    float *p_img_f, *p_txt_f;
    cudaGetSymbolAddress((void**)&p_img_f, g_img_f);
    cudaGetSymbolAddress((void**)&p_txt_f, g_txt_f);

    cudaFuncSetAttribute(k_node, cudaFuncAttributeMaxDynamicSharedMemorySize, NODE_SMEM_BYTES);
    cudaFuncSetAttribute(k_mma_gemm, cudaFuncAttributeMaxDynamicSharedMemorySize, MMA_SMEM_BYTES);

    int pairs_i = IMG_D / 2, pairs_t = TXT_D / 2;
    int prep_tot = (pairs_i + pairs_t) * 128;
    int nblocks_scan = (N + 1023) / 1024;

    // slot 3 = k_mma_gemm (ncu captures launch index 3)
    k_prep<<<(prep_tot + 255) / 256, 256>>>(W_img, W_txt, pairs_i, pairs_t);   // 0
    k_prep_node<<<(NW_PAIRS * 128 + 255) / 256, 256>>>(iW1, iW2, tW1, tW2, cW, fW); // 1
    k_zero<<<(N + 255) / 256, 256>>>(N);                        // 2
    dim3 ggrid((N + 127) / 128, 2);
    k_mma_gemm<<<ggrid, 256, MMA_SMEM_BYTES>>>(img_h, txt_h,
                                               p_img_f, p_txt_f, N, IMG_D, TXT_D); // 3
    k_count<<<(E + 255) / 256, 256>>>(dst, E);                  // 4
    k_scan1<<<nblocks_scan, 1024>>>(N);                         // 5
    k_scan2<<<1, 64>>>(nblocks_scan);                           // 6
    k_scan3<<<(N + 255) / 256, 256>>>(N, E);                    // 7
    k_scatter<<<(E + 255) / 256, 256>>>(src, dst, E);           // 8
    k_node<<<(N + 31) / 32, 256, NODE_SMEM_BYTES>>>(            // 9
        node_id, emb,
        ib1, ib2, iW3, ib3,
        tb1, tb2, tW3, tb3,
        cb, attn_a, N);
    k_agg<<<(N * 32 + 255) / 256, 256>>>(out, N);               // 10
}